// round 9
// baseline (speedup 1.0000x reference)
#include <cuda_runtime.h>
#include <cuda_fp16.h>
#include <stdint.h>

#define NN 4096
#define SB 4

#define CSPLIT   2                    // column split factor
#define ROWS_PB  16                   // rows per block (4 warps x 4 rows)
#define COLS_PB  (NN / CSPLIT)        // 2048
#define NRG      (NN / ROWS_PB)       // 256 row-groups
#define ITERS    (COLS_PB / (32 * 8)) // 8 lane-iterations

// Scratch (allocation-free requirement => __device__ globals)
__device__ __align__(16) __half g_E [(size_t)NN * NN];   // exp(-C/eps)    [n][m]
__device__ __align__(16) __half g_Et[(size_t)NN * NN];   // transpose      [m][n]
__device__ __align__(16) float  g_u [SB * NN];
__device__ __align__(16) float  g_v [SB * NN];
__device__ __align__(16) float  g_part[CSPLIT * SB * NN]; // per-half partial sums
__device__ int g_cnt[NRG];                                // row-group arrival counters

// ---------------------------------------------------------------------------
// u0 = 1; counters = 0 (counters self-reset afterwards)
__global__ void init_u_kernel() {
    int i = blockIdx.x * blockDim.x + threadIdx.x;
    if (i < SB * NN) g_u[i] = 1.0f;
    if (i < NRG)     g_cnt[i] = 0;
}

// ---------------------------------------------------------------------------
// K = exp(-C/eps) in fp16, plus transposed copy (smem tile transpose).
__global__ __launch_bounds__(256) void prep_kernel(const float* __restrict__ C,
                                                   const float* __restrict__ eps_p) {
    __shared__ __half tile[32][33];
    const float scale = -1.4426950408889634f / eps_p[0];
    const int tx = threadIdx.x, ty = threadIdx.y;
    const int x  = blockIdx.x * 32 + tx;
    const int yb = blockIdx.y * 32;
#pragma unroll
    for (int j = 0; j < 32; j += 8) {
        int y = yb + ty + j;
        float c = __ldg(&C[(size_t)y * NN + x]);
        __half h = __float2half(exp2f(c * scale));
        g_E[(size_t)y * NN + x] = h;
        tile[ty + j][tx] = h;
    }
    __syncthreads();
    const int x2  = blockIdx.y * 32 + tx;
    const int yb2 = blockIdx.x * 32;
#pragma unroll
    for (int j = 0; j < 32; j += 8)
        g_Et[(size_t)(yb2 + ty + j) * NN + x2] = tile[tx][ty + j];
}

// ---------------------------------------------------------------------------
// One Sinkhorn half-step:  xout[s][n] = ab[s][n] / sum_m M[n][m] * xin[s][m]
//
// Column-split x2 for occupancy: grid = 512 blocks of 128 threads (3 blocks/SM
// at ~150 regs => 12 warps/SM). Each block: 16 rows x 2048 cols, 4 rows/warp,
// 4 batches, packed fma.rn.f32x2. Partial sums go to g_part (plain STG,
// deterministic); the last block of each row-group (threadfence+counter) sums
// the halves in fixed order, divides, and resets the counter.
__global__ __launch_bounds__(128, 3) void pass_kernel(int dir, const float* __restrict__ ab) {
    const __half* Mh   = dir ? g_Et : g_E;
    const float*  xin  = dir ? g_v  : g_u;
    float*        xout = dir ? g_u  : g_v;

    const int rg   = blockIdx.x >> 1;      // row-group (0..255)
    const int q    = blockIdx.x & 1;       // column half
    const int warp = threadIdx.x >> 5;
    const int lane = threadIdx.x & 31;
    const int row0 = rg * ROWS_PB + warp * 4;
    const int col0 = q * COLS_PB;

    const uint4* e0 = reinterpret_cast<const uint4*>(Mh + (size_t)row0 * NN + col0);

    unsigned long long acc[4][4];
#pragma unroll
    for (int r = 0; r < 4; r++)
#pragma unroll
        for (int s = 0; s < 4; s++) acc[r][s] = 0ull;

#pragma unroll 2
    for (int it = 0; it < ITERS; ++it) {
        const int idx = it * 32 + lane;     // uint4 index within half (0..255)
        const int ci  = col0 + idx * 8;     // global first column of 8-col strip

        unsigned long long up[SB][4];
#pragma unroll
        for (int s = 0; s < SB; s++) {
            float4 a = __ldg(reinterpret_cast<const float4*>(xin + s * NN + ci));
            float4 b = __ldg(reinterpret_cast<const float4*>(xin + s * NN + ci + 4));
            asm("mov.b64 %0, {%1, %2};" : "=l"(up[s][0]) : "f"(a.x), "f"(a.y));
            asm("mov.b64 %0, {%1, %2};" : "=l"(up[s][1]) : "f"(a.z), "f"(a.w));
            asm("mov.b64 %0, {%1, %2};" : "=l"(up[s][2]) : "f"(b.x), "f"(b.y));
            asm("mov.b64 %0, {%1, %2};" : "=l"(up[s][3]) : "f"(b.z), "f"(b.w));
        }

#pragma unroll
        for (int r = 0; r < 4; r++) {
            uint4 ev;
            asm("ld.global.nc.L1::no_allocate.v4.u32 {%0,%1,%2,%3}, [%4];"
                : "=r"(ev.x), "=r"(ev.y), "=r"(ev.z), "=r"(ev.w)
                : "l"(e0 + (size_t)r * (NN / 8) + idx));
            uint32_t hw[4] = {ev.x, ev.y, ev.z, ev.w};
#pragma unroll
            for (int p = 0; p < 4; p++) {
                float2 f = __half22float2(*reinterpret_cast<const __half2*>(&hw[p]));
                unsigned long long e2;
                asm("mov.b64 %0, {%1, %2};" : "=l"(e2) : "f"(f.x), "f"(f.y));
#pragma unroll
                for (int s = 0; s < SB; s++)
                    asm("fma.rn.f32x2 %0, %1, %2, %0;" : "+l"(acc[r][s]) : "l"(e2), "l"(up[s][p]));
            }
        }
    }

    // warp reduce each (row, batch); lane0 writes the partial for this half
#pragma unroll
    for (int r = 0; r < 4; r++) {
#pragma unroll
        for (int s = 0; s < 4; s++) {
            float lo, hi;
            asm("mov.b64 {%0, %1}, %2;" : "=f"(lo), "=f"(hi) : "l"(acc[r][s]));
            float t = lo + hi;
#pragma unroll
            for (int o = 16; o; o >>= 1) t += __shfl_down_sync(0xffffffffu, t, o);
            if (lane == 0)
                g_part[(q * SB + s) * NN + row0 + r] = t;
        }
    }

    // last-block-per-row-group does the deterministic combine + divide
    __shared__ int s_last;
    __threadfence();
    __syncthreads();
    if (threadIdx.x == 0) {
        int old = atomicAdd(&g_cnt[rg], 1);
        s_last = (old == CSPLIT - 1);
    }
    __syncthreads();
    if (s_last) {
        __threadfence();
        if (threadIdx.x < ROWS_PB * SB) {          // 64 outputs
            int nl = threadIdx.x >> 2;
            int s  = threadIdx.x & 3;
            int n  = rg * ROWS_PB + nl;
            float t = __ldcv(&g_part[(0 * SB + s) * NN + n])
                    + __ldcv(&g_part[(1 * SB + s) * NN + n]);
            xout[s * NN + n] = __ldg(&ab[s * NN + n]) / t;
        }
        if (threadIdx.x == 0) g_cnt[rg] = 0;       // self-clean for next pass
    }
}

// ---------------------------------------------------------------------------
// f = eps*log(v), g = eps*log(u)
__global__ void final_kernel(float* __restrict__ out, const float* __restrict__ eps_p) {
    int i = blockIdx.x * blockDim.x + threadIdx.x;
    float eps = eps_p[0];
    if (i < SB * NN) {
        out[i]           = eps * __logf(g_v[i]);  // f
        out[SB * NN + i] = eps * __logf(g_u[i]);  // g
    }
}

// ---------------------------------------------------------------------------
extern "C" void kernel_launch(void* const* d_in, const int* in_sizes, int n_in,
                              void* d_out, int out_size) {
    const float* alpha = (const float*)d_in[0];  // (4, 4096)
    const float* beta  = (const float*)d_in[1];  // (4, 4096)
    const float* C     = (const float*)d_in[2];  // (4096, 4096)
    const float* eps   = (const float*)d_in[3];  // scalar
    float* out = (float*)d_out;                  // f then g

    init_u_kernel<<<(SB * NN + 255) / 256, 256>>>();

    dim3 pb(32, 8), pg(NN / 32, NN / 32);
    prep_kernel<<<pg, pb>>>(C, eps);

    for (int it = 0; it < 10; it++) {
        pass_kernel<<<NRG * CSPLIT, 128>>>(0, alpha);  // v = alpha / (K  u)
        pass_kernel<<<NRG * CSPLIT, 128>>>(1, beta);   // u = beta  / (K^T v)
    }

    final_kernel<<<(SB * NN + 255) / 256, 256>>>(out, eps);
}

// round 11
// speedup vs baseline: 1.3876x; 1.3876x over previous
#include <cuda_runtime.h>
#include <cuda_fp16.h>
#include <stdint.h>

#define NN 4096
#define SB 4

#define CSPLIT   2                    // column split factor
#define ROWS_PB  16                   // rows per block (4 warps x 4 rows)
#define COLS_PB  (NN / CSPLIT)        // 2048
#define NRG      (NN / ROWS_PB)       // 256 row-groups
#define ITERS    (COLS_PB / 128)      // 16 warp-steps of 128 contiguous cols

// Scratch (allocation-free requirement => __device__ globals)
__device__ __align__(16) __half g_E [(size_t)NN * NN];   // exp(-C/eps)    [n][m]
__device__ __align__(16) __half g_Et[(size_t)NN * NN];   // transpose      [m][n]
__device__ __align__(16) float  g_u [SB * NN];
__device__ __align__(16) float  g_v [SB * NN];
__device__ __align__(16) float  g_part[CSPLIT * SB * NN]; // per-half partial sums
__device__ int g_cnt[NRG];                                // row-group arrival counters

// ---------------------------------------------------------------------------
// u0 = 1; counters = 0 (counters self-reset afterwards)
__global__ void init_u_kernel() {
    int i = blockIdx.x * blockDim.x + threadIdx.x;
    if (i < SB * NN) g_u[i] = 1.0f;
    if (i < NRG)     g_cnt[i] = 0;
}

// ---------------------------------------------------------------------------
// K = exp(-C/eps) in fp16, plus transposed copy (smem tile transpose).
__global__ __launch_bounds__(256) void prep_kernel(const float* __restrict__ C,
                                                   const float* __restrict__ eps_p) {
    __shared__ __half tile[32][33];
    const float scale = -1.4426950408889634f / eps_p[0];
    const int tx = threadIdx.x, ty = threadIdx.y;
    const int x  = blockIdx.x * 32 + tx;
    const int yb = blockIdx.y * 32;
#pragma unroll
    for (int j = 0; j < 32; j += 8) {
        int y = yb + ty + j;
        float c = __ldg(&C[(size_t)y * NN + x]);
        __half h = __float2half(exp2f(c * scale));
        g_E[(size_t)y * NN + x] = h;
        tile[ty + j][tx] = h;
    }
    __syncthreads();
    const int x2  = blockIdx.y * 32 + tx;
    const int yb2 = blockIdx.x * 32;
#pragma unroll
    for (int j = 0; j < 32; j += 8)
        g_Et[(size_t)(yb2 + ty + j) * NN + x2] = tile[tx][ty + j];
}

// ---------------------------------------------------------------------------
// One Sinkhorn half-step:  xout[s][n] = ab[s][n] / sum_m M[n][m] * xin[s][m]
//
// Fully-coalesced warp strips: each warp-step covers 128 contiguous columns,
// 4 cols/lane. u loaded as v2.b64 (direct f32x2 operands), E as v2.u32 with
// L1::no_allocate + L2::evict_last (E+Et stay L2-resident across passes).
// grid = 512 blocks x 128 threads, 4 blocks/SM => 16 warps/SM, single wave.
__global__ __launch_bounds__(128, 4) void pass_kernel(int dir, const float* __restrict__ ab) {
    const __half* Mh   = dir ? g_Et : g_E;
    const float*  xin  = dir ? g_v  : g_u;
    float*        xout = dir ? g_u  : g_v;

    unsigned long long pol;
    asm("createpolicy.fractional.L2::evict_last.b64 %0, 1.0;" : "=l"(pol));

    const int rg   = blockIdx.x >> 1;      // row-group (0..255)
    const int q    = blockIdx.x & 1;       // column half
    const int warp = threadIdx.x >> 5;
    const int lane = threadIdx.x & 31;
    const int row0 = rg * ROWS_PB + warp * 4;
    const int col0 = q * COLS_PB;

    unsigned long long acc[4][4];
#pragma unroll
    for (int r = 0; r < 4; r++)
#pragma unroll
        for (int s = 0; s < 4; s++) acc[r][s] = 0ull;

#pragma unroll 2
    for (int it = 0; it < ITERS; ++it) {
        const int ci = col0 + it * 128 + lane * 4;   // 4 contiguous cols per lane

        // u: 4 batches x 4 cols, loaded directly as packed f32x2 pairs
        unsigned long long u01[SB], u23[SB];
#pragma unroll
        for (int s = 0; s < SB; s++)
            asm("ld.global.nc.v2.b64 {%0,%1}, [%2];"
                : "=l"(u01[s]), "=l"(u23[s]) : "l"(xin + s * NN + ci));

#pragma unroll
        for (int r = 0; r < 4; r++) {
            uint32_t ha, hb;   // 2x half2 = 4 E values for this row
            asm("ld.global.nc.L1::no_allocate.L2::cache_hint.v2.u32 {%0,%1}, [%2], %3;"
                : "=r"(ha), "=r"(hb)
                : "l"(Mh + (size_t)(row0 + r) * NN + ci), "l"(pol));
            float2 fa = __half22float2(*reinterpret_cast<const __half2*>(&ha));
            float2 fb = __half22float2(*reinterpret_cast<const __half2*>(&hb));
            unsigned long long e01, e23;
            asm("mov.b64 %0, {%1, %2};" : "=l"(e01) : "f"(fa.x), "f"(fa.y));
            asm("mov.b64 %0, {%1, %2};" : "=l"(e23) : "f"(fb.x), "f"(fb.y));
#pragma unroll
            for (int s = 0; s < SB; s++) {
                asm("fma.rn.f32x2 %0, %1, %2, %0;" : "+l"(acc[r][s]) : "l"(e01), "l"(u01[s]));
                asm("fma.rn.f32x2 %0, %1, %2, %0;" : "+l"(acc[r][s]) : "l"(e23), "l"(u23[s]));
            }
        }
    }

    // warp reduce each (row, batch); lane0 writes the partial for this half
#pragma unroll
    for (int r = 0; r < 4; r++) {
#pragma unroll
        for (int s = 0; s < 4; s++) {
            float lo, hi;
            asm("mov.b64 {%0, %1}, %2;" : "=f"(lo), "=f"(hi) : "l"(acc[r][s]));
            float t = lo + hi;
#pragma unroll
            for (int o = 16; o; o >>= 1) t += __shfl_down_sync(0xffffffffu, t, o);
            if (lane == 0)
                g_part[(q * SB + s) * NN + row0 + r] = t;
        }
    }

    // last-block-per-row-group does the deterministic combine + divide
    __shared__ int s_last;
    __threadfence();
    __syncthreads();
    if (threadIdx.x == 0) {
        int old = atomicAdd(&g_cnt[rg], 1);
        s_last = (old == CSPLIT - 1);
    }
    __syncthreads();
    if (s_last) {
        __threadfence();
        if (threadIdx.x < ROWS_PB * SB) {          // 64 outputs
            int nl = threadIdx.x >> 2;
            int s  = threadIdx.x & 3;
            int n  = rg * ROWS_PB + nl;
            float t = __ldcv(&g_part[(0 * SB + s) * NN + n])
                    + __ldcv(&g_part[(1 * SB + s) * NN + n]);
            xout[s * NN + n] = __ldg(&ab[s * NN + n]) / t;
        }
        if (threadIdx.x == 0) g_cnt[rg] = 0;       // self-clean for next pass
    }
}

// ---------------------------------------------------------------------------
// f = eps*log(v), g = eps*log(u)
__global__ void final_kernel(float* __restrict__ out, const float* __restrict__ eps_p) {
    int i = blockIdx.x * blockDim.x + threadIdx.x;
    float eps = eps_p[0];
    if (i < SB * NN) {
        out[i]           = eps * __logf(g_v[i]);  // f
        out[SB * NN + i] = eps * __logf(g_u[i]);  // g
    }
}

// ---------------------------------------------------------------------------
extern "C" void kernel_launch(void* const* d_in, const int* in_sizes, int n_in,
                              void* d_out, int out_size) {
    const float* alpha = (const float*)d_in[0];  // (4, 4096)
    const float* beta  = (const float*)d_in[1];  // (4, 4096)
    const float* C     = (const float*)d_in[2];  // (4096, 4096)
    const float* eps   = (const float*)d_in[3];  // scalar
    float* out = (float*)d_out;                  // f then g

    init_u_kernel<<<(SB * NN + 255) / 256, 256>>>();

    dim3 pb(32, 8), pg(NN / 32, NN / 32);
    prep_kernel<<<pg, pb>>>(C, eps);

    for (int it = 0; it < 10; it++) {
        pass_kernel<<<NRG * CSPLIT, 128>>>(0, alpha);  // v = alpha / (K  u)
        pass_kernel<<<NRG * CSPLIT, 128>>>(1, beta);   // u = beta  / (K^T v)
    }

    final_kernel<<<(SB * NN + 255) / 256, 256>>>(out, eps);
}